// round 4
// baseline (speedup 1.0000x reference)
#include <cuda_runtime.h>
#include <cuda_bf16.h>
#include <cstdint>

#define NUM_HEADS   8
#define HIDDEN_DIM  64
#define N_REAL      30000
#define N_VIRT      2000
#define N_NODES     (N_REAL + N_VIRT)
#define N_EDGES     512000
#define VEC_PER_ROW (HIDDEN_DIM / 4)   // 16 float4 per node row
#define SCAN_THREADS 1024
#define SCAN_PER     ((N_NODES + SCAN_THREADS - 1) / SCAN_THREADS)  // 32

// Scratch (device globals; allocation-free per harness rules)
__device__ float4 g_h0[N_NODES * VEC_PER_ROW];   // node features, 8 MB
__device__ float4 g_h1[N_NODES * VEC_PER_ROW];   // round-1 result, 8 MB
__device__ int    g_indeg[N_NODES];
__device__ float  g_winv[N_NODES];               // 1 / indeg
__device__ int    g_rowptr[N_NODES + 1];         // CSR row offsets (by dst)
__device__ int    g_cursor[N_NODES];             // scatter cursors
__device__ int    g_csrc[N_EDGES];               // CSR column (src) ids

// ---------------------------------------------------------------------------
// K1: in-degree histogram
__global__ void k_indeg(const int* __restrict__ dst) {
    int e = blockIdx.x * blockDim.x + threadIdx.x;
    if (e >= N_EDGES) return;
    atomicAdd(&g_indeg[dst[e]], 1);
}

// K2: single-block exclusive scan of indeg -> rowptr; also winv and cursor init.
__global__ void k_scan() {
    __shared__ int part[SCAN_THREADS];
    int t = threadIdx.x;
    int base = t * SCAN_PER;

    int s = 0;
#pragma unroll
    for (int i = 0; i < SCAN_PER; i++) {
        int idx = base + i;
        if (idx < N_NODES) s += g_indeg[idx];
    }
    part[t] = s;
    __syncthreads();

    // Hillis-Steele inclusive scan over the 1024 partials
    for (int off = 1; off < SCAN_THREADS; off <<= 1) {
        int v = (t >= off) ? part[t - off] : 0;
        __syncthreads();
        part[t] += v;
        __syncthreads();
    }
    int run = (t == 0) ? 0 : part[t - 1];   // exclusive prefix of this chunk

#pragma unroll
    for (int i = 0; i < SCAN_PER; i++) {
        int idx = base + i;
        if (idx < N_NODES) {
            int d = g_indeg[idx];
            g_rowptr[idx] = run;
            g_cursor[idx] = run;
            g_winv[idx]   = d > 0 ? (1.0f / (float)d) : 0.0f;
            run += d;
        }
    }
    if (t == SCAN_THREADS - 1) g_rowptr[N_NODES] = run;
}

// K3: scatter src ids into dst-grouped CSR order
__global__ void k_scatter(const int* __restrict__ src,
                          const int* __restrict__ dst) {
    int e = blockIdx.x * blockDim.x + threadIdx.x;
    if (e >= N_EDGES) return;
    int d = dst[e];
    int pos = atomicAdd(&g_cursor[d], 1);
    g_csrc[pos] = src[e];
}

// K4: build h0 = concat(features[cnodes], virtue_emb)
__global__ void k_build_h0(const float4* __restrict__ features,
                           const float4* __restrict__ virtue_emb,
                           const int* __restrict__ cnodes) {
    int t = blockIdx.x * blockDim.x + threadIdx.x;
    if (t >= N_NODES * VEC_PER_ROW) return;
    int v = t >> 4;
    int c = t & 15;
    float4 x;
    if (v < N_REAL) {
        int w = cnodes[v];
        x = features[(size_t)w * VEC_PER_ROW + c];
    } else {
        x = virtue_emb[(size_t)(v - N_REAL) * VEC_PER_ROW + c];
    }
    g_h0[t] = x;
}

// K5: round 1 — h1[v] = winv[v] * sum_{e: dst=v} h0[src[e]]. 16 threads/node,
// register accumulation, single coalesced write. No atomics.
__global__ void k_round1_csr() {
    int t = blockIdx.x * blockDim.x + threadIdx.x;
    if (t >= N_NODES * VEC_PER_ROW) return;
    int v = t >> 4;
    int c = t & 15;
    int beg = g_rowptr[v];
    int end = g_rowptr[v + 1];
    float4 acc = make_float4(0.f, 0.f, 0.f, 0.f);
    for (int i = beg; i < end; i++) {
        int s = g_csrc[i];                      // warp-uniform per half-warp (broadcast)
        float4 x = g_h0[s * VEC_PER_ROW + c];
        acc.x += x.x; acc.y += x.y; acc.z += x.z; acc.w += x.w;
    }
    float w = g_winv[v];
    acc.x *= w; acc.y *= w; acc.z *= w; acc.w *= w;
    g_h1[t] = acc;
}

// K6: round 2 for the 2000 virtual nodes only, fused with the 8-head
// broadcast write straight into the output.
__global__ void k_round2_csr(const int* __restrict__ vm_idx,
                             float4* __restrict__ out) {
    int t = blockIdx.x * blockDim.x + threadIdx.x;
    if (t >= N_VIRT * VEC_PER_ROW) return;
    int u = t >> 4;
    int c = t & 15;
    int v = vm_idx[u];                          // = u + N_REAL
    int beg = g_rowptr[v];
    int end = g_rowptr[v + 1];
    float4 acc = make_float4(0.f, 0.f, 0.f, 0.f);
    for (int i = beg; i < end; i++) {
        int s = g_csrc[i];
        float4 x = g_h1[s * VEC_PER_ROW + c];
        acc.x += x.x; acc.y += x.y; acc.z += x.z; acc.w += x.w;
    }
    float w = g_winv[v];
    acc.x *= w; acc.y *= w; acc.z *= w; acc.w *= w;
#pragma unroll
    for (int h = 0; h < NUM_HEADS; h++) {
        out[((size_t)u * NUM_HEADS + h) * VEC_PER_ROW + c] = acc;
    }
}

// ---------------------------------------------------------------------------
extern "C" void kernel_launch(void* const* d_in, const int* in_sizes, int n_in,
                              void* d_out, int out_size) {
    const float4* features   = (const float4*)d_in[0];  // [100000,64] f32
    const float4* virtue_emb = (const float4*)d_in[1];  // [2000,64]   f32
    const int*    cnodes     = (const int*)d_in[2];     // [30000] i32
    const int*    src        = (const int*)d_in[3];     // [512000] i32
    const int*    dst        = (const int*)d_in[4];     // [512000] i32
    const int*    vm_idx     = (const int*)d_in[5];     // [2000] i32
    float4*       out        = (float4*)d_out;          // [2000,8,64] f32

    void* p_indeg;
    cudaGetSymbolAddress(&p_indeg, g_indeg);
    cudaMemsetAsync(p_indeg, 0, sizeof(int) * N_NODES, 0);

    const int TB = 256;
    k_indeg     <<<(N_EDGES + TB - 1) / TB, TB>>>(dst);
    k_scan      <<<1, SCAN_THREADS>>>();
    k_scatter   <<<(N_EDGES + TB - 1) / TB, TB>>>(src, dst);
    k_build_h0  <<<(N_NODES * VEC_PER_ROW + TB - 1) / TB, TB>>>(features, virtue_emb, cnodes);
    k_round1_csr<<<(N_NODES * VEC_PER_ROW + TB - 1) / TB, TB>>>();
    k_round2_csr<<<(N_VIRT * VEC_PER_ROW + TB - 1) / TB, TB>>>(vm_idx, out);
}

// round 5
// speedup vs baseline: 2.0985x; 2.0985x over previous
#include <cuda_runtime.h>
#include <cuda_bf16.h>
#include <cstdint>

#define NUM_HEADS   8
#define HIDDEN_DIM  64
#define N_REAL      30000
#define N_VIRT      2000
#define N_NODES     (N_REAL + N_VIRT)
#define N_EDGES     512000
#define VEC_PER_ROW (HIDDEN_DIM / 4)   // 16 float4 per node row
#define SMALL_THREADS 1024

// Scratch (device globals; allocation-free per harness rules)
__device__ float4 g_h0[N_NODES * VEC_PER_ROW];   // node features, 8 MB
__device__ float4 g_h1[N_NODES * VEC_PER_ROW];   // round-1 accumulator, 8 MB
__device__ int    g_indeg[N_NODES];
__device__ float  g_winv[N_NODES];               // 1 / indeg
__device__ int    g_vrowptr[N_VIRT + 1];         // CSR rowptr over virtual dst only
__device__ int    g_vcursor[N_VIRT];
__device__ int    g_vsrc[N_EDGES];               // src ids of virtual-dst edges

__device__ __forceinline__ void red_add_v4(float4* addr, float4 v) {
    asm volatile("red.global.add.v4.f32 [%0], {%1,%2,%3,%4};"
                 :: "l"(addr), "f"(v.x), "f"(v.y), "f"(v.z), "f"(v.w)
                 : "memory");
}

// ---------------------------------------------------------------------------
// K1: in-degree histogram (all nodes)
__global__ void k_indeg(const int* __restrict__ dst) {
    int e = blockIdx.x * blockDim.x + threadIdx.x;
    if (e >= N_EDGES) return;
    atomicAdd(&g_indeg[dst[e]], 1);
}

// K2 (single block): winv for all nodes + exclusive scan of virtual indeg.
__global__ void k_small() {
    int t = threadIdx.x;

    // winv for all 32000 nodes, 32 per thread
#pragma unroll
    for (int i = 0; i < (N_NODES + SMALL_THREADS - 1) / SMALL_THREADS; i++) {
        int v = t + i * SMALL_THREADS;
        if (v < N_NODES) {
            int d = g_indeg[v];
            g_winv[v] = d > 0 ? (1.0f / (float)d) : 0.0f;
        }
    }

    // scan over 2000 virtual in-degrees, 2 per thread
    __shared__ int part[SMALL_THREADS];
    int d0 = 0, d1 = 0;
    int v0 = 2 * t, v1 = 2 * t + 1;
    if (v0 < N_VIRT) d0 = g_indeg[N_REAL + v0];
    if (v1 < N_VIRT) d1 = g_indeg[N_REAL + v1];
    part[t] = d0 + d1;
    __syncthreads();
    for (int off = 1; off < SMALL_THREADS; off <<= 1) {
        int x = (t >= off) ? part[t - off] : 0;
        __syncthreads();
        part[t] += x;
        __syncthreads();
    }
    int run = (t == 0) ? 0 : part[t - 1];
    if (v0 < N_VIRT) { g_vrowptr[v0] = run; g_vcursor[v0] = run; run += d0; }
    if (v1 < N_VIRT) { g_vrowptr[v1] = run; g_vcursor[v1] = run; run += d1; }
    if (t == SMALL_THREADS - 1) g_vrowptr[N_VIRT] = run;
}

// K3: build h0 = concat(features[cnodes], virtue_emb)
__global__ void k_build_h0(const float4* __restrict__ features,
                           const float4* __restrict__ virtue_emb,
                           const int* __restrict__ cnodes) {
    int t = blockIdx.x * blockDim.x + threadIdx.x;
    if (t >= N_NODES * VEC_PER_ROW) return;
    int v = t >> 4;
    int c = t & 15;
    float4 x;
    if (v < N_REAL) {
        int w = cnodes[v];
        x = features[(size_t)w * VEC_PER_ROW + c];
    } else {
        x = virtue_emb[(size_t)(v - N_REAL) * VEC_PER_ROW + c];
    }
    g_h0[t] = x;
}

// K4: round 1 — h1[dst] += h0[src] * winv[dst], all edges. 16 threads/edge.
__global__ void k_round1(const int* __restrict__ src,
                         const int* __restrict__ dst) {
    int t = blockIdx.x * blockDim.x + threadIdx.x;
    if (t >= N_EDGES * VEC_PER_ROW) return;
    int e = t >> 4;
    int c = t & 15;
    int s = src[e];
    int d = dst[e];
    float w = g_winv[d];
    float4 x = g_h0[s * VEC_PER_ROW + c];
    x.x *= w; x.y *= w; x.z *= w; x.w *= w;
    red_add_v4(&g_h1[d * VEC_PER_ROW + c], x);
}

// K5: scatter src ids of virtual-dst edges into CSR order (~32K edges)
__global__ void k_vscatter(const int* __restrict__ src,
                           const int* __restrict__ dst) {
    int e = blockIdx.x * blockDim.x + threadIdx.x;
    if (e >= N_EDGES) return;
    int d = dst[e];
    if (d < N_REAL) return;
    int pos = atomicAdd(&g_vcursor[d - N_REAL], 1);
    g_vsrc[pos] = src[e];
}

// K6: round 2 for virtual nodes only, register accumulation, fused 8-head
// broadcast straight into the output.
__global__ void k_round2v(const int* __restrict__ vm_idx,
                          float4* __restrict__ out) {
    int t = blockIdx.x * blockDim.x + threadIdx.x;
    if (t >= N_VIRT * VEC_PER_ROW) return;
    int u = t >> 4;
    int c = t & 15;
    int v = vm_idx[u];                      // = u + N_REAL
    int r = v - N_REAL;
    int beg = g_vrowptr[r];
    int end = g_vrowptr[r + 1];
    float4 acc = make_float4(0.f, 0.f, 0.f, 0.f);
    for (int i = beg; i < end; i++) {
        int s = g_vsrc[i];
        float4 x = g_h1[s * VEC_PER_ROW + c];
        acc.x += x.x; acc.y += x.y; acc.z += x.z; acc.w += x.w;
    }
    float w = g_winv[v];
    acc.x *= w; acc.y *= w; acc.z *= w; acc.w *= w;
#pragma unroll
    for (int h = 0; h < NUM_HEADS; h++) {
        out[((size_t)u * NUM_HEADS + h) * VEC_PER_ROW + c] = acc;
    }
}

// ---------------------------------------------------------------------------
extern "C" void kernel_launch(void* const* d_in, const int* in_sizes, int n_in,
                              void* d_out, int out_size) {
    const float4* features   = (const float4*)d_in[0];  // [100000,64] f32
    const float4* virtue_emb = (const float4*)d_in[1];  // [2000,64]   f32
    const int*    cnodes     = (const int*)d_in[2];     // [30000] i32
    const int*    src        = (const int*)d_in[3];     // [512000] i32
    const int*    dst        = (const int*)d_in[4];     // [512000] i32
    const int*    vm_idx     = (const int*)d_in[5];     // [2000] i32
    float4*       out        = (float4*)d_out;          // [2000,8,64] f32

    void *p_h1, *p_indeg;
    cudaGetSymbolAddress(&p_h1, g_h1);
    cudaGetSymbolAddress(&p_indeg, g_indeg);
    cudaMemsetAsync(p_indeg, 0, sizeof(int) * N_NODES, 0);
    cudaMemsetAsync(p_h1, 0, sizeof(float4) * N_NODES * VEC_PER_ROW, 0);

    const int TB = 256;
    k_indeg    <<<(N_EDGES + TB - 1) / TB, TB>>>(dst);
    k_small    <<<1, SMALL_THREADS>>>();
    k_build_h0 <<<(N_NODES * VEC_PER_ROW + TB - 1) / TB, TB>>>(features, virtue_emb, cnodes);
    k_round1   <<<(N_EDGES * VEC_PER_ROW + TB - 1) / TB, TB>>>(src, dst);
    k_vscatter <<<(N_EDGES + TB - 1) / TB, TB>>>(src, dst);
    k_round2v  <<<(N_VIRT * VEC_PER_ROW + TB - 1) / TB, TB>>>(vm_idx, out);
}

// round 6
// speedup vs baseline: 2.3090x; 1.1003x over previous
#include <cuda_runtime.h>
#include <cuda_bf16.h>
#include <cstdint>

#define NUM_HEADS   8
#define HIDDEN_DIM  64
#define N_REAL      30000
#define N_VIRT      2000
#define N_NODES     (N_REAL + N_VIRT)
#define N_EDGES     512000
#define VEC_PER_ROW (HIDDEN_DIM / 4)   // 16 float4 per node row
#define SMALL_THREADS 1024
#define TB 256

// block-range sizes for fused kernels
#define PREP_INDEG_BLOCKS  (N_EDGES / TB)                 // 2000
#define PREP_H0_BLOCKS     (N_NODES * VEC_PER_ROW / TB)   // 2000
#define PREP_ZERO_BLOCKS   (N_NODES * VEC_PER_ROW / TB)   // 2000
#define E_PER 4
#define MAIN_R1_BLOCKS     (N_EDGES / E_PER * VEC_PER_ROW / TB)  // 8000
#define MAIN_VS_BLOCKS     (N_EDGES / TB)                 // 2000

// Scratch (device globals; allocation-free per harness rules)
__device__ float4 g_h0[N_NODES * VEC_PER_ROW];   // node features, 8 MB
__device__ float4 g_h1[N_NODES * VEC_PER_ROW];   // round-1 accumulator, 8 MB
__device__ int    g_indeg[N_NODES];
__device__ float  g_winv[N_NODES];               // 1 / indeg
__device__ int    g_vrowptr[N_VIRT + 1];         // CSR rowptr over virtual dst only
__device__ int    g_vcursor[N_VIRT];
__device__ int    g_vsrc[N_EDGES];               // src ids of virtual-dst edges

__device__ __forceinline__ void red_add_v4(float4* addr, float4 v) {
    asm volatile("red.global.add.v4.f32 [%0], {%1,%2,%3,%4};"
                 :: "l"(addr), "f"(v.x), "f"(v.y), "f"(v.z), "f"(v.w)
                 : "memory");
}

// ---------------------------------------------------------------------------
// K_prep (fused, block-range dispatch):
//   role 0: in-degree histogram over all edges
//   role 1: build h0 = concat(features[cnodes], virtue_emb)
//   role 2: zero g_h1
__global__ void k_prep(const float4* __restrict__ features,
                       const float4* __restrict__ virtue_emb,
                       const int* __restrict__ cnodes,
                       const int* __restrict__ dst) {
    int b = blockIdx.x;
    if (b < PREP_INDEG_BLOCKS) {
        int e = b * TB + threadIdx.x;
        atomicAdd(&g_indeg[dst[e]], 1);
        return;
    }
    b -= PREP_INDEG_BLOCKS;
    if (b < PREP_H0_BLOCKS) {
        int t = b * TB + threadIdx.x;
        int v = t >> 4;
        int c = t & 15;
        float4 x;
        if (v < N_REAL) {
            int w = cnodes[v];
            x = features[(size_t)w * VEC_PER_ROW + c];
        } else {
            x = virtue_emb[(size_t)(v - N_REAL) * VEC_PER_ROW + c];
        }
        g_h0[t] = x;
        return;
    }
    b -= PREP_H0_BLOCKS;
    {
        int t = b * TB + threadIdx.x;
        g_h1[t] = make_float4(0.f, 0.f, 0.f, 0.f);
    }
}

// K_small (single block): winv for all nodes + exclusive scan of virtual indeg.
__global__ void k_small() {
    int t = threadIdx.x;
#pragma unroll
    for (int i = 0; i < (N_NODES + SMALL_THREADS - 1) / SMALL_THREADS; i++) {
        int v = t + i * SMALL_THREADS;
        if (v < N_NODES) {
            int d = g_indeg[v];
            g_winv[v] = d > 0 ? (1.0f / (float)d) : 0.0f;
        }
    }
    __shared__ int part[SMALL_THREADS];
    int d0 = 0, d1 = 0;
    int v0 = 2 * t, v1 = 2 * t + 1;
    if (v0 < N_VIRT) d0 = g_indeg[N_REAL + v0];
    if (v1 < N_VIRT) d1 = g_indeg[N_REAL + v1];
    part[t] = d0 + d1;
    __syncthreads();
    for (int off = 1; off < SMALL_THREADS; off <<= 1) {
        int x = (t >= off) ? part[t - off] : 0;
        __syncthreads();
        part[t] += x;
        __syncthreads();
    }
    int run = (t == 0) ? 0 : part[t - 1];
    if (v0 < N_VIRT) { g_vrowptr[v0] = run; g_vcursor[v0] = run; run += d0; }
    if (v1 < N_VIRT) { g_vrowptr[v1] = run; g_vcursor[v1] = run; run += d1; }
    if (t == SMALL_THREADS - 1) g_vrowptr[N_VIRT] = run;
}

// K_main (fused):
//   role 0: round 1 — h1[dst] += h0[src] * winv[dst]; 4 edges per thread,
//           index/weight/gather loads batched ahead of the reductions (MLP≈4).
//   role 1: scatter src ids of virtual-dst edges into CSR order.
__global__ void k_main(const int* __restrict__ src,
                       const int* __restrict__ dst) {
    int b = blockIdx.x;
    if (b < MAIN_R1_BLOCKS) {
        int t = b * TB + threadIdx.x;
        int c  = t & 15;
        int e0 = (t >> 4) * E_PER;

        int s[E_PER], d[E_PER];
#pragma unroll
        for (int j = 0; j < E_PER; j++) { s[j] = src[e0 + j]; d[j] = dst[e0 + j]; }
        float w[E_PER];
#pragma unroll
        for (int j = 0; j < E_PER; j++) w[j] = g_winv[d[j]];
        float4 x[E_PER];
#pragma unroll
        for (int j = 0; j < E_PER; j++) x[j] = g_h0[s[j] * VEC_PER_ROW + c];
#pragma unroll
        for (int j = 0; j < E_PER; j++) {
            x[j].x *= w[j]; x[j].y *= w[j]; x[j].z *= w[j]; x[j].w *= w[j];
            red_add_v4(&g_h1[d[j] * VEC_PER_ROW + c], x[j]);
        }
        return;
    }
    b -= MAIN_R1_BLOCKS;
    {
        int e = b * TB + threadIdx.x;
        int dd = dst[e];
        if (dd < N_REAL) return;
        int pos = atomicAdd(&g_vcursor[dd - N_REAL], 1);
        g_vsrc[pos] = src[e];
    }
}

// K_round2v: round 2 for virtual nodes only, register accumulation, fused
// 8-head broadcast straight into the output.
__global__ void k_round2v(const int* __restrict__ vm_idx,
                          float4* __restrict__ out) {
    int t = blockIdx.x * blockDim.x + threadIdx.x;
    if (t >= N_VIRT * VEC_PER_ROW) return;
    int u = t >> 4;
    int c = t & 15;
    int v = vm_idx[u];                      // = u + N_REAL
    int r = v - N_REAL;
    int beg = g_vrowptr[r];
    int end = g_vrowptr[r + 1];
    float4 acc = make_float4(0.f, 0.f, 0.f, 0.f);
    for (int i = beg; i < end; i++) {
        int s = g_vsrc[i];
        float4 x = g_h1[s * VEC_PER_ROW + c];
        acc.x += x.x; acc.y += x.y; acc.z += x.z; acc.w += x.w;
    }
    float w = g_winv[v];
    acc.x *= w; acc.y *= w; acc.z *= w; acc.w *= w;
#pragma unroll
    for (int h = 0; h < NUM_HEADS; h++) {
        out[((size_t)u * NUM_HEADS + h) * VEC_PER_ROW + c] = acc;
    }
}

// ---------------------------------------------------------------------------
extern "C" void kernel_launch(void* const* d_in, const int* in_sizes, int n_in,
                              void* d_out, int out_size) {
    const float4* features   = (const float4*)d_in[0];  // [100000,64] f32
    const float4* virtue_emb = (const float4*)d_in[1];  // [2000,64]   f32
    const int*    cnodes     = (const int*)d_in[2];     // [30000] i32
    const int*    src        = (const int*)d_in[3];     // [512000] i32
    const int*    dst        = (const int*)d_in[4];     // [512000] i32
    const int*    vm_idx     = (const int*)d_in[5];     // [2000] i32
    float4*       out        = (float4*)d_out;          // [2000,8,64] f32

    void* p_indeg;
    cudaGetSymbolAddress(&p_indeg, g_indeg);
    cudaMemsetAsync(p_indeg, 0, sizeof(int) * N_NODES, 0);

    k_prep   <<<PREP_INDEG_BLOCKS + PREP_H0_BLOCKS + PREP_ZERO_BLOCKS, TB>>>(
                 features, virtue_emb, cnodes, dst);
    k_small  <<<1, SMALL_THREADS>>>();
    k_main   <<<MAIN_R1_BLOCKS + MAIN_VS_BLOCKS, TB>>>(src, dst);
    k_round2v<<<(N_VIRT * VEC_PER_ROW + TB - 1) / TB, TB>>>(vm_idx, out);
}

// round 7
// speedup vs baseline: 2.3714x; 1.0270x over previous
#include <cuda_runtime.h>
#include <cuda_bf16.h>
#include <cstdint>

#define NUM_HEADS   8
#define HIDDEN_DIM  64
#define N_REAL      30000
#define N_VIRT      2000
#define N_NODES     (N_REAL + N_VIRT)
#define N_EDGES     512000
#define VEC_PER_ROW (HIDDEN_DIM / 4)   // 16 float4 per node row
#define SMALL_THREADS 1024
#define TB 256

// block-range sizes for fused kernels
#define PREP_INDEG_BLOCKS  (N_EDGES / TB)                 // 2000
#define PREP_H0_BLOCKS     (N_NODES * VEC_PER_ROW / TB)   // 2000
#define PREP_ZERO_BLOCKS   (N_NODES * VEC_PER_ROW / TB)   // 2000
#define PREP_ZERO2_BLOCKS  (N_VIRT * VEC_PER_ROW / TB)    // 125
#define E_PER 4
#define MAIN_R1_BLOCKS     (N_EDGES / E_PER * VEC_PER_ROW / TB)  // 8000
#define MAIN_VS_BLOCKS     (N_EDGES / TB)                 // 2000
#define R2_BLOCKS          2048                            // grid-stride over nv*16 threads

// Scratch (device globals; allocation-free per harness rules)
__device__ float4 g_h0[N_NODES * VEC_PER_ROW];   // node features, 8 MB
__device__ float4 g_h1[N_NODES * VEC_PER_ROW];   // round-1 accumulator, 8 MB
__device__ float4 g_h2[N_VIRT * VEC_PER_ROW];    // round-2 accumulator, 512 KB
__device__ int    g_indeg[N_NODES];
__device__ float  g_winv[N_NODES];               // 1 / indeg
__device__ int    g_vrowptr[N_VIRT + 1];         // CSR rowptr over virtual dst only
__device__ int    g_vcursor[N_VIRT];
__device__ int    g_vsrc[N_EDGES];               // src ids of virtual-dst edges
__device__ int    g_vdst[N_EDGES];               // matching virtual dst (0..N_VIRT-1)

__device__ __forceinline__ void red_add_v4(float4* addr, float4 v) {
    asm volatile("red.global.add.v4.f32 [%0], {%1,%2,%3,%4};"
                 :: "l"(addr), "f"(v.x), "f"(v.y), "f"(v.z), "f"(v.w)
                 : "memory");
}

// ---------------------------------------------------------------------------
// K_prep (fused, block-range dispatch):
//   role 0: in-degree histogram over all edges
//   role 1: build h0 = concat(features[cnodes], virtue_emb)
//   role 2: zero g_h1
//   role 3: zero g_h2
__global__ void k_prep(const float4* __restrict__ features,
                       const float4* __restrict__ virtue_emb,
                       const int* __restrict__ cnodes,
                       const int* __restrict__ dst) {
    int b = blockIdx.x;
    if (b < PREP_INDEG_BLOCKS) {
        int e = b * TB + threadIdx.x;
        atomicAdd(&g_indeg[dst[e]], 1);
        return;
    }
    b -= PREP_INDEG_BLOCKS;
    if (b < PREP_H0_BLOCKS) {
        int t = b * TB + threadIdx.x;
        int v = t >> 4;
        int c = t & 15;
        float4 x;
        if (v < N_REAL) {
            int w = cnodes[v];
            x = features[(size_t)w * VEC_PER_ROW + c];
        } else {
            x = virtue_emb[(size_t)(v - N_REAL) * VEC_PER_ROW + c];
        }
        g_h0[t] = x;
        return;
    }
    b -= PREP_H0_BLOCKS;
    if (b < PREP_ZERO_BLOCKS) {
        int t = b * TB + threadIdx.x;
        g_h1[t] = make_float4(0.f, 0.f, 0.f, 0.f);
        return;
    }
    b -= PREP_ZERO_BLOCKS;
    {
        int t = b * TB + threadIdx.x;
        g_h2[t] = make_float4(0.f, 0.f, 0.f, 0.f);
    }
}

// K_small (single block): winv for all nodes + exclusive scan of virtual indeg.
__global__ void k_small() {
    int t = threadIdx.x;
#pragma unroll
    for (int i = 0; i < (N_NODES + SMALL_THREADS - 1) / SMALL_THREADS; i++) {
        int v = t + i * SMALL_THREADS;
        if (v < N_NODES) {
            int d = g_indeg[v];
            g_winv[v] = d > 0 ? (1.0f / (float)d) : 0.0f;
        }
    }
    __shared__ int part[SMALL_THREADS];
    int d0 = 0, d1 = 0;
    int v0 = 2 * t, v1 = 2 * t + 1;
    if (v0 < N_VIRT) d0 = g_indeg[N_REAL + v0];
    if (v1 < N_VIRT) d1 = g_indeg[N_REAL + v1];
    part[t] = d0 + d1;
    __syncthreads();
    for (int off = 1; off < SMALL_THREADS; off <<= 1) {
        int x = (t >= off) ? part[t - off] : 0;
        __syncthreads();
        part[t] += x;
        __syncthreads();
    }
    int run = (t == 0) ? 0 : part[t - 1];
    if (v0 < N_VIRT) { g_vrowptr[v0] = run; g_vcursor[v0] = run; run += d0; }
    if (v1 < N_VIRT) { g_vrowptr[v1] = run; g_vcursor[v1] = run; run += d1; }
    if (t == SMALL_THREADS - 1) g_vrowptr[N_VIRT] = run;
}

// K_main (fused):
//   role 0: round 1 — h1[dst] += h0[src] * winv[dst]; 4 edges per thread,
//           index/weight/gather loads batched ahead of the reductions (MLP≈4).
//   role 1: compact virtual-dst edges into (g_vsrc, g_vdst).
__global__ void k_main(const int* __restrict__ src,
                       const int* __restrict__ dst) {
    int b = blockIdx.x;
    if (b < MAIN_R1_BLOCKS) {
        int t = b * TB + threadIdx.x;
        int c  = t & 15;
        int e0 = (t >> 4) * E_PER;

        int s[E_PER], d[E_PER];
#pragma unroll
        for (int j = 0; j < E_PER; j++) { s[j] = src[e0 + j]; d[j] = dst[e0 + j]; }
        float w[E_PER];
#pragma unroll
        for (int j = 0; j < E_PER; j++) w[j] = g_winv[d[j]];
        float4 x[E_PER];
#pragma unroll
        for (int j = 0; j < E_PER; j++) x[j] = g_h0[s[j] * VEC_PER_ROW + c];
#pragma unroll
        for (int j = 0; j < E_PER; j++) {
            x[j].x *= w[j]; x[j].y *= w[j]; x[j].z *= w[j]; x[j].w *= w[j];
            red_add_v4(&g_h1[d[j] * VEC_PER_ROW + c], x[j]);
        }
        return;
    }
    b -= MAIN_R1_BLOCKS;
    {
        int e = b * TB + threadIdx.x;
        int dd = dst[e];
        if (dd < N_REAL) return;
        int pos = atomicAdd(&g_vcursor[dd - N_REAL], 1);
        g_vsrc[pos] = src[e];
        g_vdst[pos] = dd - N_REAL;
    }
}

// K_round2e: edge-parallel round 2 over the compacted virtual-dst edges.
// 16 lanes per edge; grid-stride over nv (read on device). No serial chains.
__global__ void k_round2e() {
    int nv = g_vrowptr[N_VIRT];              // total virtual-dst edges
    int total = nv * VEC_PER_ROW;
    for (int t = blockIdx.x * blockDim.x + threadIdx.x; t < total;
         t += gridDim.x * blockDim.x) {
        int e = t >> 4;
        int c = t & 15;
        int s = g_vsrc[e];
        int r = g_vdst[e];
        float4 x = g_h1[s * VEC_PER_ROW + c];
        red_add_v4(&g_h2[r * VEC_PER_ROW + c], x);
    }
}

// K_bcast: scale by winv and broadcast across the 8 identical heads.
__global__ void k_bcast(const int* __restrict__ vm_idx,
                        float4* __restrict__ out) {
    int t = blockIdx.x * blockDim.x + threadIdx.x;
    if (t >= N_VIRT * VEC_PER_ROW) return;
    int u = t >> 4;
    int c = t & 15;
    int r = vm_idx[u] - N_REAL;              // = u
    float w = g_winv[r + N_REAL];
    float4 x = g_h2[r * VEC_PER_ROW + c];
    x.x *= w; x.y *= w; x.z *= w; x.w *= w;
#pragma unroll
    for (int h = 0; h < NUM_HEADS; h++) {
        out[((size_t)u * NUM_HEADS + h) * VEC_PER_ROW + c] = x;
    }
}

// ---------------------------------------------------------------------------
extern "C" void kernel_launch(void* const* d_in, const int* in_sizes, int n_in,
                              void* d_out, int out_size) {
    const float4* features   = (const float4*)d_in[0];  // [100000,64] f32
    const float4* virtue_emb = (const float4*)d_in[1];  // [2000,64]   f32
    const int*    cnodes     = (const int*)d_in[2];     // [30000] i32
    const int*    src        = (const int*)d_in[3];     // [512000] i32
    const int*    dst        = (const int*)d_in[4];     // [512000] i32
    const int*    vm_idx     = (const int*)d_in[5];     // [2000] i32
    float4*       out        = (float4*)d_out;          // [2000,8,64] f32

    void* p_indeg;
    cudaGetSymbolAddress(&p_indeg, g_indeg);
    cudaMemsetAsync(p_indeg, 0, sizeof(int) * N_NODES, 0);

    k_prep   <<<PREP_INDEG_BLOCKS + PREP_H0_BLOCKS + PREP_ZERO_BLOCKS +
                PREP_ZERO2_BLOCKS, TB>>>(features, virtue_emb, cnodes, dst);
    k_small  <<<1, SMALL_THREADS>>>();
    k_main   <<<MAIN_R1_BLOCKS + MAIN_VS_BLOCKS, TB>>>(src, dst);
    k_round2e<<<R2_BLOCKS, TB>>>();
    k_bcast  <<<(N_VIRT * VEC_PER_ROW + TB - 1) / TB, TB>>>(vm_idx, out);
}

// round 8
// speedup vs baseline: 3.0225x; 1.2746x over previous
#include <cuda_runtime.h>
#include <cuda_fp16.h>
#include <cstdint>

#define NUM_HEADS   8
#define HIDDEN_DIM  64
#define N_REAL      30000
#define N_VIRT      2000
#define N_NODES     (N_REAL + N_VIRT)
#define N_EDGES     512000
#define VEC_PER_ROW (HIDDEN_DIM / 4)   // 16 float4 (or uint2-of-half4) per node row
#define TB 256
#define N_REP 4                        // h2 replicas to de-contend REDG

// fused-kernel block ranges
#define PREP_INDEG_BLOCKS  (N_EDGES / TB)                  // 2000
#define PREP_H0_BLOCKS     (N_NODES * VEC_PER_ROW / TB)    // 2000
#define PREP_ZERO1_BLOCKS  (N_NODES * VEC_PER_ROW / TB)    // 2000
#define PREP_VPAIR_BLOCKS  (N_EDGES / TB)                  // 2000
#define PREP_ZERO2_BLOCKS  (N_VIRT * VEC_PER_ROW * N_REP / TB) // 500
#define E_PER 4
#define R1_BLOCKS          (N_EDGES / E_PER * VEC_PER_ROW / TB) // 8000
#define R2_BLOCKS          2048

// ---- device scratch (allocation-free) --------------------------------------
struct Zeroed {                         // zeroed with ONE memsetAsync
    int indeg[N_NODES];
    int vcnt;
    unsigned char needed[N_NODES];
};
__device__ Zeroed  g_z;
__device__ __half2 g_h0h[N_NODES * 32];            // f16 node features, 4 MB
__device__ float4  g_h1[N_NODES * VEC_PER_ROW];    // round-1 raw sums, 8 MB
__device__ float4  g_h2[N_REP][N_VIRT * VEC_PER_ROW]; // round-2 replicas, 2 MB
__device__ int     g_vsrc[N_EDGES];                // virtual-dst edge src ids
__device__ int     g_vdst[N_EDGES];                // matching virtual dst (0..N_VIRT-1)

__device__ __forceinline__ void red_add_v4(float4* addr, float4 v) {
    asm volatile("red.global.add.v4.f32 [%0], {%1,%2,%3,%4};"
                 :: "l"(addr), "f"(v.x), "f"(v.y), "f"(v.z), "f"(v.w)
                 : "memory");
}
__device__ __forceinline__ float winv_of(int node) {
    float di = (float)g_z.indeg[node];
    return di > 0.f ? __frcp_rn(di) : 0.f;
}

// ---------------------------------------------------------------------------
// K_prep (fused, block-range dispatch):
//   A: in-degree histogram     B: build f16 h0     C: zero h1
//   D: append (src, dst-N_REAL) pairs for virtual-dst edges + mark needed[src]
//   E: zero h2 replicas
__global__ void k_prep(const float4* __restrict__ features,
                       const float4* __restrict__ virtue_emb,
                       const int* __restrict__ cnodes,
                       const int* __restrict__ src,
                       const int* __restrict__ dst) {
    int b = blockIdx.x;
    if (b < PREP_INDEG_BLOCKS) {
        int e = b * TB + threadIdx.x;
        atomicAdd(&g_z.indeg[dst[e]], 1);
        return;
    }
    b -= PREP_INDEG_BLOCKS;
    if (b < PREP_H0_BLOCKS) {
        int t = b * TB + threadIdx.x;
        int v = t >> 4;
        int c = t & 15;
        float4 x;
        if (v < N_REAL) {
            int w = cnodes[v];
            x = features[(size_t)w * VEC_PER_ROW + c];
        } else {
            x = virtue_emb[(size_t)(v - N_REAL) * VEC_PER_ROW + c];
        }
        g_h0h[t * 2]     = __floats2half2_rn(x.x, x.y);
        g_h0h[t * 2 + 1] = __floats2half2_rn(x.z, x.w);
        return;
    }
    b -= PREP_H0_BLOCKS;
    if (b < PREP_ZERO1_BLOCKS) {
        int t = b * TB + threadIdx.x;
        g_h1[t] = make_float4(0.f, 0.f, 0.f, 0.f);
        return;
    }
    b -= PREP_ZERO1_BLOCKS;
    if (b < PREP_VPAIR_BLOCKS) {
        int e = b * TB + threadIdx.x;
        int dd = dst[e];
        if (dd < N_REAL) return;
        int s = src[e];
        int pos = atomicAdd(&g_z.vcnt, 1);
        g_vsrc[pos] = s;
        g_vdst[pos] = dd - N_REAL;
        g_z.needed[s] = 1;               // benign race
        return;
    }
    b -= PREP_VPAIR_BLOCKS;
    {
        int t = b * TB + threadIdx.x;
        ((float4*)g_h2)[t] = make_float4(0.f, 0.f, 0.f, 0.f);
    }
}

// K_round1: h1raw[d] += h0f16[s] for edges whose dst is needed.
// 16 lanes per edge, 4 edges per thread, loads batched for MLP.
__global__ void k_round1(const int* __restrict__ src,
                         const int* __restrict__ dst) {
    int t = blockIdx.x * TB + threadIdx.x;
    int c  = t & 15;
    int e0 = (t >> 4) * E_PER;

    int s[E_PER], d[E_PER];
#pragma unroll
    for (int j = 0; j < E_PER; j++) { s[j] = src[e0 + j]; d[j] = dst[e0 + j]; }
    unsigned char f[E_PER];
#pragma unroll
    for (int j = 0; j < E_PER; j++) f[j] = g_z.needed[d[j]];

    const uint2* h0 = reinterpret_cast<const uint2*>(g_h0h);
    uint2 q[E_PER];
#pragma unroll
    for (int j = 0; j < E_PER; j++)
        if (f[j]) q[j] = h0[s[j] * VEC_PER_ROW + c];
#pragma unroll
    for (int j = 0; j < E_PER; j++) {
        if (!f[j]) continue;
        __half2 a = *reinterpret_cast<__half2*>(&q[j].x);
        __half2 bb = *reinterpret_cast<__half2*>(&q[j].y);
        float2 fa = __half22float2(a);
        float2 fb = __half22float2(bb);
        red_add_v4(&g_h1[d[j] * VEC_PER_ROW + c],
                   make_float4(fa.x, fa.y, fb.x, fb.y));
    }
}

// K_round2e: edge-parallel round 2 over appended (src, vdst) pairs.
// x = h1raw[s] * winv[s]; reduce into one of 4 h2 replicas.
__global__ void k_round2e() {
    int nv = g_z.vcnt;
    int total = nv * VEC_PER_ROW;
    int rep = (threadIdx.x >> 5) & (N_REP - 1);
    for (int t = blockIdx.x * blockDim.x + threadIdx.x; t < total;
         t += gridDim.x * blockDim.x) {
        int e = t >> 4;
        int c = t & 15;
        int s = g_vsrc[e];
        int r = g_vdst[e];
        float w = winv_of(s);
        float4 x = g_h1[s * VEC_PER_ROW + c];
        x.x *= w; x.y *= w; x.z *= w; x.w *= w;
        red_add_v4(&g_h2[rep][r * VEC_PER_ROW + c], x);
    }
}

// K_bcast: sum replicas, scale by winv[dst], broadcast across 8 heads.
__global__ void k_bcast(const int* __restrict__ vm_idx,
                        float4* __restrict__ out) {
    int t = blockIdx.x * blockDim.x + threadIdx.x;
    if (t >= N_VIRT * VEC_PER_ROW) return;
    int u = t >> 4;
    int c = t & 15;
    int r = vm_idx[u] - N_REAL;
    int idx = r * VEC_PER_ROW + c;
    float4 acc = make_float4(0.f, 0.f, 0.f, 0.f);
#pragma unroll
    for (int k = 0; k < N_REP; k++) {
        float4 x = g_h2[k][idx];
        acc.x += x.x; acc.y += x.y; acc.z += x.z; acc.w += x.w;
    }
    float w = winv_of(r + N_REAL);
    acc.x *= w; acc.y *= w; acc.z *= w; acc.w *= w;
#pragma unroll
    for (int h = 0; h < NUM_HEADS; h++) {
        out[((size_t)u * NUM_HEADS + h) * VEC_PER_ROW + c] = acc;
    }
}

// ---------------------------------------------------------------------------
extern "C" void kernel_launch(void* const* d_in, const int* in_sizes, int n_in,
                              void* d_out, int out_size) {
    const float4* features   = (const float4*)d_in[0];  // [100000,64] f32
    const float4* virtue_emb = (const float4*)d_in[1];  // [2000,64]   f32
    const int*    cnodes     = (const int*)d_in[2];     // [30000] i32
    const int*    src        = (const int*)d_in[3];     // [512000] i32
    const int*    dst        = (const int*)d_in[4];     // [512000] i32
    const int*    vm_idx     = (const int*)d_in[5];     // [2000] i32
    float4*       out        = (float4*)d_out;          // [2000,8,64] f32

    void* p_z;
    cudaGetSymbolAddress(&p_z, g_z);
    cudaMemsetAsync(p_z, 0, sizeof(Zeroed), 0);

    k_prep   <<<PREP_INDEG_BLOCKS + PREP_H0_BLOCKS + PREP_ZERO1_BLOCKS +
                PREP_VPAIR_BLOCKS + PREP_ZERO2_BLOCKS, TB>>>(
                 features, virtue_emb, cnodes, src, dst);
    k_round1 <<<R1_BLOCKS, TB>>>(src, dst);
    k_round2e<<<R2_BLOCKS, TB>>>();
    k_bcast  <<<(N_VIRT * VEC_PER_ROW + TB - 1) / TB, TB>>>(vm_idx, out);
}

// round 9
// speedup vs baseline: 3.0246x; 1.0007x over previous
#include <cuda_runtime.h>
#include <cuda_fp16.h>
#include <cstdint>

#define NUM_HEADS   8
#define HIDDEN_DIM  64
#define N_REAL      30000
#define N_VIRT      2000
#define N_NODES     (N_REAL + N_VIRT)
#define N_EDGES     512000
#define VEC_PER_ROW (HIDDEN_DIM / 4)   // 16 float4 (or uint2-of-half4) per node row
#define TB 256
#define N_REP 4                        // h2 replicas to de-contend REDG

// fused-kernel block ranges
#define PREP_INDEG_BLOCKS  (N_EDGES / TB)                  // 2000
#define PREP_H0_BLOCKS     (N_NODES * VEC_PER_ROW / TB)    // 2000
#define PREP_ZERO1_BLOCKS  (N_NODES * VEC_PER_ROW / TB)    // 2000
#define PREP_VPAIR_BLOCKS  (N_EDGES / TB)                  // 2000
#define PREP_ZERO2_BLOCKS  (N_VIRT * VEC_PER_ROW * N_REP / TB) // 500
#define E_PER 4
#define R1_BLOCKS          (N_EDGES / E_PER * VEC_PER_ROW / TB) // 8000
#define R2_BLOCKS          2048
#define BCAST_THREADS      (N_VIRT * NUM_HEADS * VEC_PER_ROW)   // 256000

// ---- device scratch (allocation-free) --------------------------------------
struct Zeroed {                         // zeroed with ONE memsetAsync
    int indeg[N_NODES];
    int vcnt;
    unsigned char needed[N_NODES];
};
__device__ Zeroed  g_z;
__device__ __half2 g_h0h[N_NODES * 32];            // f16 node features, 4 MB
__device__ float4  g_h1[N_NODES * VEC_PER_ROW];    // round-1 raw sums, 8 MB
__device__ float4  g_h2[N_REP][N_VIRT * VEC_PER_ROW]; // round-2 replicas, 2 MB
__device__ int     g_vsrc[N_EDGES];                // virtual-dst edge src ids
__device__ int     g_vdst[N_EDGES];                // matching virtual dst (0..N_VIRT-1)

__device__ __forceinline__ void red_add_v4(float4* addr, float4 v) {
    asm volatile("red.global.add.v4.f32 [%0], {%1,%2,%3,%4};"
                 :: "l"(addr), "f"(v.x), "f"(v.y), "f"(v.z), "f"(v.w)
                 : "memory");
}
__device__ __forceinline__ float winv_of(int node) {
    float di = (float)g_z.indeg[node];
    return di > 0.f ? __frcp_rn(di) : 0.f;
}

// ---------------------------------------------------------------------------
// K_prep (fused, block-range dispatch):
//   A: in-degree histogram     B: build f16 h0     C: zero h1
//   D: append (src, dst-N_REAL) pairs for virtual-dst edges + mark needed[src]
//   E: zero h2 replicas
__global__ void k_prep(const float4* __restrict__ features,
                       const float4* __restrict__ virtue_emb,
                       const int* __restrict__ cnodes,
                       const int* __restrict__ src,
                       const int* __restrict__ dst) {
    int b = blockIdx.x;
    if (b < PREP_INDEG_BLOCKS) {
        int e = b * TB + threadIdx.x;
        atomicAdd(&g_z.indeg[dst[e]], 1);
        return;
    }
    b -= PREP_INDEG_BLOCKS;
    if (b < PREP_H0_BLOCKS) {
        int t = b * TB + threadIdx.x;
        int v = t >> 4;
        int c = t & 15;
        float4 x;
        if (v < N_REAL) {
            int w = cnodes[v];
            x = features[(size_t)w * VEC_PER_ROW + c];
        } else {
            x = virtue_emb[(size_t)(v - N_REAL) * VEC_PER_ROW + c];
        }
        g_h0h[t * 2]     = __floats2half2_rn(x.x, x.y);
        g_h0h[t * 2 + 1] = __floats2half2_rn(x.z, x.w);
        return;
    }
    b -= PREP_H0_BLOCKS;
    if (b < PREP_ZERO1_BLOCKS) {
        int t = b * TB + threadIdx.x;
        g_h1[t] = make_float4(0.f, 0.f, 0.f, 0.f);
        return;
    }
    b -= PREP_ZERO1_BLOCKS;
    if (b < PREP_VPAIR_BLOCKS) {
        int e = b * TB + threadIdx.x;
        int dd = dst[e];
        if (dd < N_REAL) return;
        int s = src[e];
        int pos = atomicAdd(&g_z.vcnt, 1);
        g_vsrc[pos] = s;
        g_vdst[pos] = dd - N_REAL;
        g_z.needed[s] = 1;               // benign race
        return;
    }
    b -= PREP_VPAIR_BLOCKS;
    {
        int t = b * TB + threadIdx.x;
        ((float4*)g_h2)[t] = make_float4(0.f, 0.f, 0.f, 0.f);
    }
}

// K_round1: h1raw[d] += h0f16[s] for edges whose dst is needed.
// 16 lanes per edge, 4 edges per thread, loads batched for MLP.
__global__ void k_round1(const int* __restrict__ src,
                         const int* __restrict__ dst) {
    int t = blockIdx.x * TB + threadIdx.x;
    int c  = t & 15;
    int e0 = (t >> 4) * E_PER;

    int s[E_PER], d[E_PER];
#pragma unroll
    for (int j = 0; j < E_PER; j++) { s[j] = src[e0 + j]; d[j] = dst[e0 + j]; }
    unsigned char f[E_PER];
#pragma unroll
    for (int j = 0; j < E_PER; j++) f[j] = g_z.needed[d[j]];

    const uint2* h0 = reinterpret_cast<const uint2*>(g_h0h);
    uint2 q[E_PER];
#pragma unroll
    for (int j = 0; j < E_PER; j++)
        if (f[j]) q[j] = h0[s[j] * VEC_PER_ROW + c];
#pragma unroll
    for (int j = 0; j < E_PER; j++) {
        if (!f[j]) continue;
        __half2 a = *reinterpret_cast<__half2*>(&q[j].x);
        __half2 bb = *reinterpret_cast<__half2*>(&q[j].y);
        float2 fa = __half22float2(a);
        float2 fb = __half22float2(bb);
        red_add_v4(&g_h1[d[j] * VEC_PER_ROW + c],
                   make_float4(fa.x, fa.y, fb.x, fb.y));
    }
}

// K_round2e: edge-parallel round 2 over appended (src, vdst) pairs.
// x = h1raw[s] * winv[s]; reduce into one of 4 h2 replicas.
__global__ void k_round2e() {
    int nv = g_z.vcnt;
    int total = nv * VEC_PER_ROW;
    int rep = (threadIdx.x >> 5) & (N_REP - 1);
    for (int t = blockIdx.x * blockDim.x + threadIdx.x; t < total;
         t += gridDim.x * blockDim.x) {
        int e = t >> 4;
        int c = t & 15;
        int s = g_vsrc[e];
        int r = g_vdst[e];
        float w = winv_of(s);
        float4 x = g_h1[s * VEC_PER_ROW + c];
        x.x *= w; x.y *= w; x.z *= w; x.w *= w;
        red_add_v4(&g_h2[rep][r * VEC_PER_ROW + c], x);
    }
}

// K_bcast: one thread per OUTPUT float4 (2000*8*16 = 256K threads).
// Sums the 4 replicas (L2-broadcast reads), scales by winv[dst], one
// coalesced 16B store each. 1000 blocks — latency fully hidden.
__global__ void k_bcast(const int* __restrict__ vm_idx,
                        float4* __restrict__ out) {
    int t = blockIdx.x * blockDim.x + threadIdx.x;
    if (t >= BCAST_THREADS) return;
    int c = t & 15;
    int u = t >> 7;                         // (u, h, c) with h implicit in t
    int r = vm_idx[u] - N_REAL;
    int idx = r * VEC_PER_ROW + c;
    float4 acc = make_float4(0.f, 0.f, 0.f, 0.f);
#pragma unroll
    for (int k = 0; k < N_REP; k++) {
        float4 x = g_h2[k][idx];
        acc.x += x.x; acc.y += x.y; acc.z += x.z; acc.w += x.w;
    }
    float w = winv_of(r + N_REAL);
    acc.x *= w; acc.y *= w; acc.z *= w; acc.w *= w;
    out[t] = acc;                           // t == (u*8 + h)*16 + c
}

// ---------------------------------------------------------------------------
extern "C" void kernel_launch(void* const* d_in, const int* in_sizes, int n_in,
                              void* d_out, int out_size) {
    const float4* features   = (const float4*)d_in[0];  // [100000,64] f32
    const float4* virtue_emb = (const float4*)d_in[1];  // [2000,64]   f32
    const int*    cnodes     = (const int*)d_in[2];     // [30000] i32
    const int*    src        = (const int*)d_in[3];     // [512000] i32
    const int*    dst        = (const int*)d_in[4];     // [512000] i32
    const int*    vm_idx     = (const int*)d_in[5];     // [2000] i32
    float4*       out        = (float4*)d_out;          // [2000,8,64] f32

    void* p_z;
    cudaGetSymbolAddress(&p_z, g_z);
    cudaMemsetAsync(p_z, 0, sizeof(Zeroed), 0);

    k_prep   <<<PREP_INDEG_BLOCKS + PREP_H0_BLOCKS + PREP_ZERO1_BLOCKS +
                PREP_VPAIR_BLOCKS + PREP_ZERO2_BLOCKS, TB>>>(
                 features, virtue_emb, cnodes, src, dst);
    k_round1 <<<R1_BLOCKS, TB>>>(src, dst);
    k_round2e<<<R2_BLOCKS, TB>>>();
    k_bcast  <<<(BCAST_THREADS + TB - 1) / TB, TB>>>(vm_idx, out);
}